// round 6
// baseline (speedup 1.0000x reference)
#include <cuda_runtime.h>
#include <cuda_bf16.h>
#include <cstdint>
#include <float.h>
#include <math.h>

// Problem constants
#define BB 4
#define KK 8
#define VV 32000
#define EE 512
#define HH 1024
#define TT 64
#define NR 32            // B*K rows

// ---------------- device scratch (static: no allocation allowed) ----------------
__device__ __nv_bfloat16 g_Whi[(size_t)VV * HH];
__device__ __nv_bfloat16 g_Wlo[(size_t)VV * HH];
__device__ float         g_hid[2][NR * HH];
__device__ __nv_bfloat16 g_Bhi[NR * HH];
__device__ __nv_bfloat16 g_Blo[NR * HH];
__device__ float         g_logits[(size_t)NR * VV];
__device__ float         g_rc[NR];        // prev_vals - logsumexp per row
__device__ float         g_prevvals[NR];
__device__ int           g_prevtok[NR];
__device__ int           g_last[NR];
__device__ int           g_which[NR];     // absolute source row for hidden gather
__device__ float         g_lph[2][NR * TT];
__device__ int           g_tkh[2][NR * TT];

// ---------------- PTX helpers ----------------
__device__ __forceinline__ uint32_t smem_u32(const void* p) {
    return (uint32_t)__cvta_generic_to_shared(p);
}
__device__ __forceinline__ void cp16(uint32_t dst, const void* src) {
    asm volatile("cp.async.cg.shared.global [%0], [%1], 16;\n" :: "r"(dst), "l"(src));
}
__device__ __forceinline__ void cp_commit() { asm volatile("cp.async.commit_group;\n"); }
__device__ __forceinline__ void cp_wait1()  { asm volatile("cp.async.wait_group 1;\n"); }
__device__ __forceinline__ void cp_wait0()  { asm volatile("cp.async.wait_group 0;\n"); }

__device__ __forceinline__ void ldm4(uint32_t a[4], uint32_t addr) {
    asm volatile("ldmatrix.sync.aligned.m8n8.x4.shared.b16 {%0,%1,%2,%3}, [%4];\n"
                 : "=r"(a[0]), "=r"(a[1]), "=r"(a[2]), "=r"(a[3]) : "r"(addr));
}
__device__ __forceinline__ void mma16816(float c[4], const uint32_t a[4], const uint32_t b[2]) {
    asm volatile("mma.sync.aligned.m16n8k16.row.col.f32.bf16.bf16.f32 "
                 "{%0,%1,%2,%3},{%4,%5,%6,%7},{%8,%9},{%0,%1,%2,%3};\n"
                 : "+f"(c[0]), "+f"(c[1]), "+f"(c[2]), "+f"(c[3])
                 : "r"(a[0]), "r"(a[1]), "r"(a[2]), "r"(a[3]), "r"(b[0]), "r"(b[1]));
}

// ---------------- 1. W_out -> bf16 hi/lo split ----------------
__global__ void conv_kernel(const float* __restrict__ W) {
    size_t n = (size_t)VV * HH;
    for (size_t i = (size_t)blockIdx.x * blockDim.x + threadIdx.x; i < n;
         i += (size_t)gridDim.x * blockDim.x) {
        float w = W[i];
        __nv_bfloat16 hi = __float2bfloat16(w);
        g_Whi[i] = hi;
        g_Wlo[i] = __float2bfloat16(w - __bfloat162float(hi));
    }
}

// ---------------- 2. init ----------------
__global__ void init_kernel(const int* __restrict__ bosp) {
    int tid = threadIdx.x;
    if (tid < NR) {
        g_last[tid]     = bosp[0];
        g_prevvals[tid] = 0.0f;
        g_prevtok[tid]  = -1;   // nothing finished
    }
}

// ---------------- 3. fused embedding-gather + hidden-gather + GRU cell ----------------
// warp-per-unit: lanes = rows (N<=32), warp id = unit u. grid 128 x 256 (8 warps/blk).
__global__ __launch_bounds__(256) void gru_kernel(
    int t, int N,
    const float* __restrict__ encoded,
    const float* __restrict__ emb,
    const float* __restrict__ Wih,
    const float* __restrict__ Whh,
    const float* __restrict__ bih,
    const float* __restrict__ bhh)
{
    int u = blockIdx.x * 8 + (threadIdx.x >> 5);   // 0..1023
    int r = threadIdx.x & 31;
    if (r >= N) return;

    const float* hp;
    if (t == 0) hp = encoded + (size_t)r * HH;
    else        hp = g_hid[(t - 1) & 1] + (size_t)g_which[r] * HH;
    const float* xp = emb + (size_t)g_last[r] * EE;

    float ar = 0.f, az = 0.f, an = 0.f;
    {
        const float* w0 = Wih + (size_t)u * EE;
        const float* w1 = Wih + (size_t)(HH + u) * EE;
        const float* w2 = Wih + (size_t)(2 * HH + u) * EE;
#pragma unroll 4
        for (int e = 0; e < EE; e += 4) {
            float4 x = *reinterpret_cast<const float4*>(xp + e);
            float4 a = *reinterpret_cast<const float4*>(w0 + e);
            float4 b = *reinterpret_cast<const float4*>(w1 + e);
            float4 c = *reinterpret_cast<const float4*>(w2 + e);
            ar += x.x * a.x + x.y * a.y + x.z * a.z + x.w * a.w;
            az += x.x * b.x + x.y * b.y + x.z * b.z + x.w * b.w;
            an += x.x * c.x + x.y * c.y + x.z * c.z + x.w * c.w;
        }
    }
    float hr = 0.f, hz = 0.f, hn = 0.f;
    {
        const float* v0 = Whh + (size_t)u * HH;
        const float* v1 = Whh + (size_t)(HH + u) * HH;
        const float* v2 = Whh + (size_t)(2 * HH + u) * HH;
#pragma unroll 4
        for (int e = 0; e < HH; e += 4) {
            float4 h = *reinterpret_cast<const float4*>(hp + e);
            float4 a = *reinterpret_cast<const float4*>(v0 + e);
            float4 b = *reinterpret_cast<const float4*>(v1 + e);
            float4 c = *reinterpret_cast<const float4*>(v2 + e);
            hr += h.x * a.x + h.y * a.y + h.z * a.z + h.w * a.w;
            hz += h.x * b.x + h.y * b.y + h.z * b.z + h.w * b.w;
            hn += h.x * c.x + h.y * c.y + h.z * c.z + h.w * c.w;
        }
    }
    float rg = 1.0f / (1.0f + expf(-(ar + hr + bih[u] + bhh[u])));
    float zg = 1.0f / (1.0f + expf(-(az + hz + bih[HH + u] + bhh[HH + u])));
    float ng = tanhf(an + bih[2 * HH + u] + rg * (hn + bhh[2 * HH + u]));
    float h2 = (1.0f - zg) * ng + zg * hp[u];

    g_hid[t & 1][r * HH + u] = h2;
    __nv_bfloat16 hi = __float2bfloat16(h2);
    g_Bhi[r * HH + u] = hi;
    g_Blo[r * HH + u] = __float2bfloat16(h2 - __bfloat162float(hi));
}

// ---------------- 4. logits GEMM: split-bf16 tensor core ----------------
// M=32000 (W rows), N=32 (h rows), K=1024. Mtile=128, KT=64, 2-stage cp.async.
#define KT 64
#define KS 72   // padded bf16 stride -> conflict-free ldmatrix / LDS
#define LG_SMEM ((2*128*KS + 2*128*KS + 2*32*KS + 2*32*KS) * 2)  // 92160 bytes

__global__ __launch_bounds__(128) void logits_kernel(const float* __restrict__ b_out) {
    extern __shared__ __nv_bfloat16 sm[];
    __nv_bfloat16* sAhi = sm;                    // [2][128][KS]
    __nv_bfloat16* sAlo = sAhi + 2 * 128 * KS;
    __nv_bfloat16* sBhi = sAlo + 2 * 128 * KS;   // [2][32][KS]
    __nv_bfloat16* sBlo = sBhi + 2 * 32 * KS;

    int tid = threadIdx.x, warp = tid >> 5, lane = tid & 31;
    int v0 = blockIdx.x * 128;

    float acc[2][4][4];
#pragma unroll
    for (int m = 0; m < 2; m++)
#pragma unroll
        for (int n = 0; n < 4; n++)
#pragma unroll
            for (int f = 0; f < 4; f++) acc[m][n][f] = 0.0f;

    auto issue = [&](int kc, int st) {
        const __nv_bfloat16* gh = g_Whi + (size_t)(v0 + tid) * HH + kc * KT;
        const __nv_bfloat16* gl = g_Wlo + (size_t)(v0 + tid) * HH + kc * KT;
        uint32_t dh = smem_u32(&sAhi[(st * 128 + tid) * KS]);
        uint32_t dl = smem_u32(&sAlo[(st * 128 + tid) * KS]);
#pragma unroll
        for (int q = 0; q < 8; q++) {
            cp16(dh + q * 16, gh + q * 8);
            cp16(dl + q * 16, gl + q * 8);
        }
#pragma unroll
        for (int i = tid; i < 512; i += 128) {
            int prec = i >> 8, rem = i & 255;
            int row = rem >> 3, q = rem & 7;
            const __nv_bfloat16* src = (prec ? g_Blo : g_Bhi) + row * HH + kc * KT + q * 8;
            __nv_bfloat16* d = (prec ? sBlo : sBhi) + (st * 32 + row) * KS + q * 8;
            cp16(smem_u32(d), src);
        }
    };

    issue(0, 0);
    cp_commit();

    const int NC = HH / KT;  // 16
    for (int kc = 0; kc < NC; kc++) {
        int st = kc & 1;
        if (kc + 1 < NC) { issue(kc + 1, st ^ 1); cp_commit(); cp_wait1(); }
        else             { cp_wait0(); }
        __syncthreads();

#pragma unroll
        for (int kk = 0; kk < KT / 16; kk++) {
            int kb = kk * 16;
            uint32_t ahi[2][4], alo[2][4];
#pragma unroll
            for (int mt = 0; mt < 2; mt++) {
                int row = st * 128 + warp * 32 + mt * 16 + (lane & 15);
                int col = kb + ((lane >> 4) << 3);
                ldm4(ahi[mt], smem_u32(&sAhi[row * KS + col]));
                ldm4(alo[mt], smem_u32(&sAlo[row * KS + col]));
            }
            uint32_t bhi[4][2], blo[4][2];
#pragma unroll
            for (int nt = 0; nt < 4; nt++) {
                int n = st * 32 + nt * 8 + (lane >> 2);
                int c = kb + ((lane & 3) << 1);
                bhi[nt][0] = *(const uint32_t*)&sBhi[n * KS + c];
                bhi[nt][1] = *(const uint32_t*)&sBhi[n * KS + c + 8];
                blo[nt][0] = *(const uint32_t*)&sBlo[n * KS + c];
                blo[nt][1] = *(const uint32_t*)&sBlo[n * KS + c + 8];
            }
#pragma unroll
            for (int mt = 0; mt < 2; mt++)
#pragma unroll
                for (int nt = 0; nt < 4; nt++) {
                    mma16816(acc[mt][nt], ahi[mt], bhi[nt]);
                    mma16816(acc[mt][nt], ahi[mt], blo[nt]);
                    mma16816(acc[mt][nt], alo[mt], bhi[nt]);
                }
        }
        __syncthreads();
    }

    // epilogue: transpose through smem, coalesced store with bias
    float* sOut = (float*)sm;   // [32][132]
#pragma unroll
    for (int mt = 0; mt < 2; mt++)
#pragma unroll
        for (int nt = 0; nt < 4; nt++) {
            int vl = warp * 32 + mt * 16 + (lane >> 2);
            int n0 = nt * 8 + ((lane & 3) << 1);
            sOut[n0 * 132 + vl]           = acc[mt][nt][0];
            sOut[(n0 + 1) * 132 + vl]     = acc[mt][nt][1];
            sOut[n0 * 132 + vl + 8]       = acc[mt][nt][2];
            sOut[(n0 + 1) * 132 + vl + 8] = acc[mt][nt][3];
        }
    __syncthreads();
#pragma unroll
    for (int i = tid; i < 32 * 128; i += 128) {
        int n = i >> 7, vl = i & 127;
        g_logits[(size_t)n * VV + v0 + vl] = sOut[n * 132 + vl] + b_out[v0 + vl];
    }
}

// ---------------- 5. per-row max + logsumexp -> rc ----------------
__global__ __launch_bounds__(256) void rowstats_kernel() {
    int r = blockIdx.x, tid = threadIdx.x;
    const float* lg = g_logits + (size_t)r * VV;
    __shared__ float red[256];
    float m = -FLT_MAX;
    for (int v = tid; v < VV; v += 256) m = fmaxf(m, lg[v]);
    red[tid] = m; __syncthreads();
    for (int o = 128; o > 0; o >>= 1) { if (tid < o) red[tid] = fmaxf(red[tid], red[tid + o]); __syncthreads(); }
    m = red[0]; __syncthreads();
    float s = 0.f;
    for (int v = tid; v < VV; v += 256) s += __expf(lg[v] - m);
    red[tid] = s; __syncthreads();
    for (int o = 128; o > 0; o >>= 1) { if (tid < o) red[tid] += red[tid + o]; __syncthreads(); }
    if (tid == 0) g_rc[r] = g_prevvals[r] - (m + logf(red[0]));
}

// ---------------- 6. top-k machinery ----------------
__device__ __forceinline__ bool betterf(float va, int ia, float vb, int ib) {
    return (va > vb) || (va == vb && ia < ib);   // JAX top_k tie-break: lower index wins
}

// merge-tree of sorted-8 lists in smem; result in sv[0..8) of thread 0
__device__ __forceinline__ void merge_topk(float* sv, int* si, int tid) {
    for (int off = 128; off >= 1; off >>= 1) {
        if (tid < off) {
            int pa = tid * 8, pb = (tid + off) * 8;
            float rv[8]; int ri[8];
            int ia = 0, ib = 0;
#pragma unroll
            for (int j = 0; j < 8; j++) {
                float va = sv[pa + ia], vb = sv[pb + ib];
                int   xa = si[pa + ia], xb = si[pb + ib];
                bool ta = betterf(va, xa, vb, xb);
                rv[j] = ta ? va : vb; ri[j] = ta ? xa : xb;
                ia += ta; ib += !ta;
            }
#pragma unroll
            for (int j = 0; j < 8; j++) { sv[pa + j] = rv[j]; si[pa + j] = ri[j]; }
        }
        __syncthreads();
    }
}

#define INS_DECL float lv[8]; int li[8]; \
    _Pragma("unroll") for (int j = 0; j < 8; j++) { lv[j] = -FLT_MAX; li[j] = 0x7FFFFFFF; }

#define INS(vx, ix) do { float _v = (vx); int _i = (ix); \
    if (betterf(_v, _i, lv[7], li[7])) { \
        bool placed = false; \
        _Pragma("unroll") for (int j = 7; j >= 1; j--) { \
            if (!placed) { \
                if (betterf(_v, _i, lv[j-1], li[j-1])) { lv[j] = lv[j-1]; li[j] = li[j-1]; } \
                else { lv[j] = _v; li[j] = _i; placed = true; } } } \
        if (!placed) { lv[0] = _v; li[0] = _i; } } } while (0)

// step 0: plain top-8 of log-softmax per batch row
__global__ __launch_bounds__(256) void topk0_kernel() {
    __shared__ float sv[2048]; __shared__ int si[2048];
    __shared__ float s_val[8]; __shared__ int s_tok[8];
    int b = blockIdx.x, tid = threadIdx.x;
    float rc = g_rc[b];
    const float* lg = g_logits + (size_t)b * VV;
    INS_DECL
    for (int v = tid; v < VV; v += 256) INS(lg[v] + rc, v);
#pragma unroll
    for (int j = 0; j < 8; j++) { sv[tid * 8 + j] = lv[j]; si[tid * 8 + j] = li[j]; }
    __syncthreads();
    merge_topk(sv, si, tid);
    if (tid < 8) {
        float v = sv[tid]; int tok = si[tid];
        s_val[tid] = v; s_tok[tid] = tok;
        int row = b * 8 + tid;
        g_prevvals[row] = v; g_prevtok[row] = tok; g_last[row] = tok;
        g_which[row] = b;   // hidden source: row b of the 4-row h0
    }
    __syncthreads();
    for (int i = tid; i < 8 * TT; i += 256) {
        int k = i >> 6, s = i & 63;
        g_lph[0][(b * 8 + k) * TT + s] = (s == 0) ? s_val[k] : 0.0f;
        g_tkh[0][(b * 8 + k) * TT + s] = (s == 0) ? s_tok[k] : 0;
    }
}

// steps t>=1: top-8 over K*V with eos masking, beam-state update + history gather
__global__ __launch_bounds__(256) void topk_kernel(int t, const int* __restrict__ eosp) {
    __shared__ float sv[2048]; __shared__ int si[2048];
    __shared__ float s_val[8]; __shared__ int s_tok[8], s_wk[8];
    int b = blockIdx.x, tid = threadIdx.x;
    int eos = eosp[0];
    INS_DECL
    for (int k = 0; k < 8; k++) {
        int row = b * 8 + k;
        if (g_prevtok[row] == eos) {
            // finished: only the eos continuation survives, with value exactly 0.0
            if (tid == 0) INS(0.0f, k * VV + eos);
        } else {
            float rc = g_rc[row];
            const float* lg = g_logits + (size_t)row * VV;
            for (int v = tid; v < VV; v += 256) INS(lg[v] + rc, k * VV + v);
        }
    }
#pragma unroll
    for (int j = 0; j < 8; j++) { sv[tid * 8 + j] = lv[j]; si[tid * 8 + j] = li[j]; }
    __syncthreads();
    merge_topk(sv, si, tid);
    if (tid < 8) {
        float v = sv[tid]; int id = si[tid];
        int tok = id % VV, wk = id / VV;
        s_val[tid] = v; s_tok[tid] = tok; s_wk[tid] = wk;
        int row = b * 8 + tid;
        g_prevvals[row] = v; g_prevtok[row] = tok; g_last[row] = tok;
        g_which[row] = b * 8 + wk;
    }
    __syncthreads();
    int nb = t & 1, ob = nb ^ 1;
    for (int i = tid; i < 8 * TT; i += 256) {
        int k = i >> 6, s = i & 63;
        int dst = (b * 8 + k) * TT + s;
        int srcrow = b * 8 + s_wk[k];
        float lp; int tk;
        if (s < t)      { lp = g_lph[ob][srcrow * TT + s]; tk = g_tkh[ob][srcrow * TT + s]; }
        else if (s == t){ lp = s_val[k]; tk = s_tok[k]; }
        else            { lp = 0.0f;     tk = 0; }
        g_lph[nb][dst] = lp; g_tkh[nb][dst] = tk;
    }
}

// ---------------- 7. output ----------------
__global__ void fin_kernel(float* __restrict__ out, int n) {
    int i = blockIdx.x * blockDim.x + threadIdx.x;
    if (i >= n) return;
    if (i < NR * TT)          out[i] = g_lph[1][i];
    else if (i < 2 * NR * TT) out[i] = (float)g_tkh[1][i - NR * TT];
    else                      out[i] = 0.0f;
}

// ---------------- launch ----------------
extern "C" void kernel_launch(void* const* d_in, const int* in_sizes, int n_in,
                              void* d_out, int out_size) {
    const float* encoded   = (const float*)d_in[0];
    const float* embedding = (const float*)d_in[1];
    const float* W_ih      = (const float*)d_in[2];
    const float* W_hh      = (const float*)d_in[3];
    const float* b_ih      = (const float*)d_in[4];
    const float* b_hh      = (const float*)d_in[5];
    const float* W_out     = (const float*)d_in[6];
    const float* b_out     = (const float*)d_in[7];
    const int*   bos       = (const int*)d_in[8];
    const int*   eos       = (const int*)d_in[9];

    cudaFuncSetAttribute(logits_kernel, cudaFuncAttributeMaxDynamicSharedMemorySize, LG_SMEM);

    conv_kernel<<<1024, 256>>>(W_out);
    init_kernel<<<1, 32>>>(bos);

    for (int t = 0; t < TT; t++) {
        int N = (t == 0) ? BB : NR;
        gru_kernel<<<128, 256>>>(t, N, encoded, embedding, W_ih, W_hh, b_ih, b_hh);
        logits_kernel<<<250, 128, LG_SMEM>>>(b_out);
        rowstats_kernel<<<N, 256>>>();
        if (t == 0) topk0_kernel<<<BB, 256>>>();
        else        topk_kernel<<<BB, 256>>>(t, eos);
    }
    fin_kernel<<<(out_size + 255) / 256, 256>>>((float*)d_out, out_size);
}

// round 7
// speedup vs baseline: 2.0904x; 2.0904x over previous
#include <cuda_runtime.h>
#include <cuda_bf16.h>
#include <cstdint>
#include <float.h>
#include <math.h>

// Problem constants
#define BB 4
#define KK 8
#define VV 32000
#define EE 512
#define HH 1024
#define TT 64
#define NR 32            // B*K rows

// ---------------- device scratch (static: no allocation allowed) ----------------
__device__ __nv_bfloat16 g_Whi[(size_t)VV * HH];
__device__ __nv_bfloat16 g_Wlo[(size_t)VV * HH];
__device__ float         g_hid[2][NR * HH];
__device__ __nv_bfloat16 g_Bhi[NR * HH];
__device__ __nv_bfloat16 g_Blo[NR * HH];
__device__ float         g_logits[(size_t)NR * VV];
__device__ float         g_rc[NR];        // prev_vals - logsumexp per row
__device__ float         g_prevvals[NR];
__device__ int           g_prevtok[NR];
__device__ int           g_last[NR];
__device__ int           g_which[NR];     // absolute source row for hidden gather
__device__ float         g_cv[NR][8];     // per-row top-8 raw logit values (sorted)
__device__ int           g_ci[NR][8];     // per-row top-8 vocab indices
__device__ float         g_lph[2][NR * TT];
__device__ int           g_tkh[2][NR * TT];

// ---------------- PTX helpers ----------------
__device__ __forceinline__ uint32_t smem_u32(const void* p) {
    return (uint32_t)__cvta_generic_to_shared(p);
}
__device__ __forceinline__ void cp16(uint32_t dst, const void* src) {
    asm volatile("cp.async.cg.shared.global [%0], [%1], 16;\n" :: "r"(dst), "l"(src));
}
__device__ __forceinline__ void cp_commit() { asm volatile("cp.async.commit_group;\n"); }
__device__ __forceinline__ void cp_wait2()  { asm volatile("cp.async.wait_group 2;\n"); }
__device__ __forceinline__ void cp_wait1()  { asm volatile("cp.async.wait_group 1;\n"); }
__device__ __forceinline__ void cp_wait0()  { asm volatile("cp.async.wait_group 0;\n"); }

__device__ __forceinline__ void ldm4(uint32_t a[4], uint32_t addr) {
    asm volatile("ldmatrix.sync.aligned.m8n8.x4.shared.b16 {%0,%1,%2,%3}, [%4];\n"
                 : "=r"(a[0]), "=r"(a[1]), "=r"(a[2]), "=r"(a[3]) : "r"(addr));
}
__device__ __forceinline__ void mma16816(float c[4], const uint32_t a[4], const uint32_t b[2]) {
    asm volatile("mma.sync.aligned.m16n8k16.row.col.f32.bf16.bf16.f32 "
                 "{%0,%1,%2,%3},{%4,%5,%6,%7},{%8,%9},{%0,%1,%2,%3};\n"
                 : "+f"(c[0]), "+f"(c[1]), "+f"(c[2]), "+f"(c[3])
                 : "r"(a[0]), "r"(a[1]), "r"(a[2]), "r"(a[3]), "r"(b[0]), "r"(b[1]));
}

// ---------------- 1. W_out -> bf16 hi/lo split ----------------
__global__ void conv_kernel(const float* __restrict__ W) {
    size_t n = (size_t)VV * HH;
    for (size_t i = (size_t)blockIdx.x * blockDim.x + threadIdx.x; i < n;
         i += (size_t)gridDim.x * blockDim.x) {
        float w = W[i];
        __nv_bfloat16 hi = __float2bfloat16(w);
        g_Whi[i] = hi;
        g_Wlo[i] = __float2bfloat16(w - __bfloat162float(hi));
    }
}

// ---------------- 2. init ----------------
__global__ void init_kernel(const int* __restrict__ bosp) {
    int tid = threadIdx.x;
    if (tid < NR) {
        g_last[tid]     = bosp[0];
        g_prevvals[tid] = 0.0f;
        g_prevtok[tid]  = -1;   // nothing finished
    }
}

// ---------------- 3. GRU: smem-staged x/h (transposed), warp-per-unit ----------------
// grid 128 x 256. Block stages x[N][512], h[N][1024] transposed with stride-33 pad
// (conflict-free lane-per-row LDS.32); weight rows are warp-uniform broadcasts.
#define GRU_SMEM ((512 * 33 + 1024 * 33) * 4)   // 202752 bytes

__global__ __launch_bounds__(256) void gru_kernel(
    int t, int N,
    const float* __restrict__ encoded,
    const float* __restrict__ emb,
    const float* __restrict__ Wih,
    const float* __restrict__ Whh,
    const float* __restrict__ bih,
    const float* __restrict__ bhh)
{
    extern __shared__ float sg[];
    float* sx = sg;             // [512][33]  sx[e*33+r]
    float* sh = sg + 512 * 33;  // [1024][33] sh[e*33+r]
    int tid = threadIdx.x;

    // stage x (embedding gather) coalesced on global, conflict-free smem writes
    for (int i = tid; i < N * EE; i += 256) {
        int r = i >> 9, e = i & 511;
        sx[e * 33 + r] = emb[(size_t)g_last[r] * EE + e];
    }
    // stage h (beam-gathered hidden)
    for (int i = tid; i < N * HH; i += 256) {
        int r = i >> 10, e = i & 1023;
        const float* hb = (t == 0) ? (encoded + (size_t)r * HH)
                                   : (g_hid[(t - 1) & 1] + (size_t)g_which[r] * HH);
        sh[e * 33 + r] = hb[e];
    }
    __syncthreads();

    int u = blockIdx.x * 8 + (tid >> 5);   // unit 0..1023
    int r = tid & 31;                      // beam row

    float ar = 0.f, az = 0.f, an = 0.f;
    {
        const float* w0 = Wih + (size_t)u * EE;
        const float* w1 = Wih + (size_t)(HH + u) * EE;
        const float* w2 = Wih + (size_t)(2 * HH + u) * EE;
#pragma unroll 4
        for (int e = 0; e < EE; e += 4) {
            float4 a = *reinterpret_cast<const float4*>(w0 + e);
            float4 b = *reinterpret_cast<const float4*>(w1 + e);
            float4 c = *reinterpret_cast<const float4*>(w2 + e);
            float x0 = sx[e * 33 + r], x1 = sx[(e + 1) * 33 + r];
            float x2 = sx[(e + 2) * 33 + r], x3 = sx[(e + 3) * 33 + r];
            ar += x0 * a.x + x1 * a.y + x2 * a.z + x3 * a.w;
            az += x0 * b.x + x1 * b.y + x2 * b.z + x3 * b.w;
            an += x0 * c.x + x1 * c.y + x2 * c.z + x3 * c.w;
        }
    }
    float hr = 0.f, hz = 0.f, hn = 0.f;
    {
        const float* v0 = Whh + (size_t)u * HH;
        const float* v1 = Whh + (size_t)(HH + u) * HH;
        const float* v2 = Whh + (size_t)(2 * HH + u) * HH;
#pragma unroll 4
        for (int e = 0; e < HH; e += 4) {
            float4 a = *reinterpret_cast<const float4*>(v0 + e);
            float4 b = *reinterpret_cast<const float4*>(v1 + e);
            float4 c = *reinterpret_cast<const float4*>(v2 + e);
            float h0 = sh[e * 33 + r], h1 = sh[(e + 1) * 33 + r];
            float h2v = sh[(e + 2) * 33 + r], h3 = sh[(e + 3) * 33 + r];
            hr += h0 * a.x + h1 * a.y + h2v * a.z + h3 * a.w;
            hz += h0 * b.x + h1 * b.y + h2v * b.z + h3 * b.w;
            hn += h0 * c.x + h1 * c.y + h2v * c.z + h3 * c.w;
        }
    }
    if (r < N) {
        float rg = 1.0f / (1.0f + expf(-(ar + hr + bih[u] + bhh[u])));
        float zg = 1.0f / (1.0f + expf(-(az + hz + bih[HH + u] + bhh[HH + u])));
        float ng = tanhf(an + bih[2 * HH + u] + rg * (hn + bhh[2 * HH + u]));
        float h2 = (1.0f - zg) * ng + zg * sh[u * 33 + r];

        g_hid[t & 1][r * HH + u] = h2;
        __nv_bfloat16 hi = __float2bfloat16(h2);
        g_Bhi[r * HH + u] = hi;
        g_Blo[r * HH + u] = __float2bfloat16(h2 - __bfloat162float(hi));
    }
}

// ---------------- 4. logits GEMM: split-bf16 tensor core, 4-stage cp.async ----------------
// M=32000, N=32, K=1024. Mtile=128, KT=32, 4 stages (3 in flight).
#define KT 32
#define KS 40   // padded bf16 stride -> conflict-free ldmatrix / LDS
#define NST 4
#define LG_SMEM ((NST * 128 * KS * 2 + NST * 32 * KS * 2) * 2)  // 102400 bytes

__global__ __launch_bounds__(128) void logits_kernel(const float* __restrict__ b_out) {
    extern __shared__ __nv_bfloat16 sm[];
    __nv_bfloat16* sAhi = sm;                        // [NST][128][KS]
    __nv_bfloat16* sAlo = sAhi + NST * 128 * KS;
    __nv_bfloat16* sBhi = sAlo + NST * 128 * KS;     // [NST][32][KS]
    __nv_bfloat16* sBlo = sBhi + NST * 32 * KS;

    int tid = threadIdx.x, warp = tid >> 5, lane = tid & 31;
    int v0 = blockIdx.x * 128;

    float acc[2][4][4];
#pragma unroll
    for (int m = 0; m < 2; m++)
#pragma unroll
        for (int n = 0; n < 4; n++)
#pragma unroll
            for (int f = 0; f < 4; f++) acc[m][n][f] = 0.0f;

    auto issue = [&](int kc, int st) {
        const __nv_bfloat16* gh = g_Whi + (size_t)(v0 + tid) * HH + kc * KT;
        const __nv_bfloat16* gl = g_Wlo + (size_t)(v0 + tid) * HH + kc * KT;
        uint32_t dh = smem_u32(&sAhi[(st * 128 + tid) * KS]);
        uint32_t dl = smem_u32(&sAlo[(st * 128 + tid) * KS]);
#pragma unroll
        for (int q = 0; q < 4; q++) {
            cp16(dh + q * 16, gh + q * 8);
            cp16(dl + q * 16, gl + q * 8);
        }
#pragma unroll
        for (int i = tid; i < 256; i += 128) {
            int prec = i >> 7, rem = i & 127;
            int row = rem >> 2, q = rem & 3;
            const __nv_bfloat16* src = (prec ? g_Blo : g_Bhi) + row * HH + kc * KT + q * 8;
            __nv_bfloat16* d = (prec ? sBlo : sBhi) + (st * 32 + row) * KS + q * 8;
            cp16(smem_u32(d), src);
        }
    };

    const int NC = HH / KT;  // 32
    issue(0, 0); cp_commit();
    issue(1, 1); cp_commit();
    issue(2, 2); cp_commit();

    for (int kc = 0; kc < NC; kc++) {
        int st = kc & (NST - 1);
        int rem = NC - 1 - kc;
        if (rem >= 2)      cp_wait2();
        else if (rem == 1) cp_wait1();
        else               cp_wait0();
        __syncthreads();
        if (kc + 3 < NC) { issue(kc + 3, (kc + 3) & (NST - 1)); cp_commit(); }

#pragma unroll
        for (int kk = 0; kk < KT / 16; kk++) {
            int kb = kk * 16;
            uint32_t ahi[2][4], alo[2][4];
#pragma unroll
            for (int mt = 0; mt < 2; mt++) {
                int row = st * 128 + warp * 32 + mt * 16 + (lane & 15);
                int col = kb + ((lane >> 4) << 3);
                ldm4(ahi[mt], smem_u32(&sAhi[row * KS + col]));
                ldm4(alo[mt], smem_u32(&sAlo[row * KS + col]));
            }
            uint32_t bhi[4][2], blo[4][2];
#pragma unroll
            for (int nt = 0; nt < 4; nt++) {
                int n = st * 32 + nt * 8 + (lane >> 2);
                int c = kb + ((lane & 3) << 1);
                bhi[nt][0] = *(const uint32_t*)&sBhi[n * KS + c];
                bhi[nt][1] = *(const uint32_t*)&sBhi[n * KS + c + 8];
                blo[nt][0] = *(const uint32_t*)&sBlo[n * KS + c];
                blo[nt][1] = *(const uint32_t*)&sBlo[n * KS + c + 8];
            }
#pragma unroll
            for (int mt = 0; mt < 2; mt++)
#pragma unroll
                for (int nt = 0; nt < 4; nt++) {
                    mma16816(acc[mt][nt], ahi[mt], bhi[nt]);
                    mma16816(acc[mt][nt], ahi[mt], blo[nt]);
                    mma16816(acc[mt][nt], alo[mt], bhi[nt]);
                }
        }
        __syncthreads();
    }

    // epilogue: transpose through smem, coalesced store with bias
    float* sOut = (float*)sm;   // [32][132]
#pragma unroll
    for (int mt = 0; mt < 2; mt++)
#pragma unroll
        for (int nt = 0; nt < 4; nt++) {
            int vl = warp * 32 + mt * 16 + (lane >> 2);
            int n0 = nt * 8 + ((lane & 3) << 1);
            sOut[n0 * 132 + vl]           = acc[mt][nt][0];
            sOut[(n0 + 1) * 132 + vl]     = acc[mt][nt][1];
            sOut[n0 * 132 + vl + 8]       = acc[mt][nt][2];
            sOut[(n0 + 1) * 132 + vl + 8] = acc[mt][nt][3];
        }
    __syncthreads();
#pragma unroll
    for (int i = tid; i < 32 * 128; i += 128) {
        int n = i >> 7, vl = i & 127;
        g_logits[(size_t)n * VV + v0 + vl] = sOut[n * 132 + vl] + b_out[v0 + vl];
    }
}

// ---------------- 5. top-k machinery ----------------
__device__ __forceinline__ bool betterf(float va, int ia, float vb, int ib) {
    return (va > vb) || (va == vb && ia < ib);   // JAX top_k tie-break: lower index wins
}

__device__ __forceinline__ void merge_topk(float* sv, int* si, int tid) {
    for (int off = 128; off >= 1; off >>= 1) {
        if (tid < off) {
            int pa = tid * 8, pb = (tid + off) * 8;
            float rv[8]; int ri[8];
            int ia = 0, ib = 0;
#pragma unroll
            for (int j = 0; j < 8; j++) {
                float va = sv[pa + ia], vb = sv[pb + ib];
                int   xa = si[pa + ia], xb = si[pb + ib];
                bool ta = betterf(va, xa, vb, xb);
                rv[j] = ta ? va : vb; ri[j] = ta ? xa : xb;
                ia += ta; ib += !ta;
            }
#pragma unroll
            for (int j = 0; j < 8; j++) { sv[pa + j] = rv[j]; si[pa + j] = ri[j]; }
        }
        __syncthreads();
    }
}

#define INS_DECL float lv[8]; int li[8]; \
    _Pragma("unroll") for (int j = 0; j < 8; j++) { lv[j] = -FLT_MAX; li[j] = 0x7FFFFFFF; }

#define INS(vx, ix) do { float _v = (vx); int _i = (ix); \
    if (betterf(_v, _i, lv[7], li[7])) { \
        bool placed = false; \
        _Pragma("unroll") for (int j = 7; j >= 1; j--) { \
            if (!placed) { \
                if (betterf(_v, _i, lv[j-1], li[j-1])) { lv[j] = lv[j-1]; li[j] = li[j-1]; } \
                else { lv[j] = _v; li[j] = _i; placed = true; } } } \
        if (!placed) { lv[0] = _v; li[0] = _i; } } } while (0)

// phase 1: per-row (fused rowstats + raw-logit top-8). grid = N rows.
__global__ __launch_bounds__(256) void topk1_kernel() {
    __shared__ float red[256];
    __shared__ float sv[2048]; __shared__ int si[2048];
    int r = blockIdx.x, tid = threadIdx.x;
    const float4* lg4 = (const float4*)(g_logits + (size_t)r * VV);

    float m = -FLT_MAX;
    INS_DECL
#pragma unroll 2
    for (int i = tid; i < VV / 4; i += 256) {
        float4 x = lg4[i];
        int v = i * 4;
        m = fmaxf(m, fmaxf(fmaxf(x.x, x.y), fmaxf(x.z, x.w)));
        INS(x.x, v); INS(x.y, v + 1); INS(x.z, v + 2); INS(x.w, v + 3);
    }
    red[tid] = m; __syncthreads();
    for (int o = 128; o > 0; o >>= 1) { if (tid < o) red[tid] = fmaxf(red[tid], red[tid + o]); __syncthreads(); }
    m = red[0]; __syncthreads();

    float s = 0.f;
#pragma unroll 2
    for (int i = tid; i < VV / 4; i += 256) {
        float4 x = lg4[i];
        s += __expf(x.x - m) + __expf(x.y - m) + __expf(x.z - m) + __expf(x.w - m);
    }
    red[tid] = s; __syncthreads();
    for (int o = 128; o > 0; o >>= 1) { if (tid < o) red[tid] += red[tid + o]; __syncthreads(); }
    if (tid == 0) g_rc[r] = g_prevvals[r] - (m + logf(red[0]));

#pragma unroll
    for (int j = 0; j < 8; j++) { sv[tid * 8 + j] = lv[j]; si[tid * 8 + j] = li[j]; }
    __syncthreads();
    merge_topk(sv, si, tid);
    if (tid < 8) { g_cv[r][tid] = sv[tid]; g_ci[r][tid] = si[tid]; }
}

// phase 2: per-batch merge of 8x8 candidates, eos masking, beam update + history gather
__global__ __launch_bounds__(256) void merge_kernel(int t, const int* __restrict__ eosp) {
    __shared__ float cv[64]; __shared__ int ci[64];
    __shared__ float s_val[8]; __shared__ int s_tok[8], s_wk[8];
    int b = blockIdx.x, tid = threadIdx.x;
    int eos = eosp[0];
    int ncand = (t == 0) ? 8 : 64;

    if (t == 0) {
        if (tid < 8) { cv[tid] = g_cv[b][tid] + g_rc[b]; ci[tid] = g_ci[b][tid]; }
    } else if (tid < 64) {
        int k = tid >> 3, j = tid & 7, row = b * 8 + k;
        if (g_prevtok[row] == eos) {
            cv[tid] = (j == 0) ? 0.0f : -FLT_MAX;
            ci[tid] = (j == 0) ? (k * VV + eos) : 0x7FFFFFFF;
        } else {
            cv[tid] = g_cv[row][j] + g_rc[row];
            ci[tid] = k * VV + g_ci[row][j];
        }
    }
    __syncthreads();

    if (tid == 0) {
        INS_DECL
        for (int i = 0; i < ncand; i++) INS(cv[i], ci[i]);
        for (int j = 0; j < 8; j++) {
            float v = lv[j]; int id = li[j];
            int tok = (t == 0) ? id : (id % VV);
            int wk  = (t == 0) ? 0  : (id / VV);
            s_val[j] = v; s_tok[j] = tok; s_wk[j] = wk;
            int row = b * 8 + j;
            g_prevvals[row] = v; g_prevtok[row] = tok; g_last[row] = tok;
            g_which[row] = (t == 0) ? b : (b * 8 + wk);
        }
    }
    __syncthreads();

    if (t == 0) {
        for (int i = tid; i < 8 * TT; i += 256) {
            int k = i >> 6, s = i & 63;
            g_lph[0][(b * 8 + k) * TT + s] = (s == 0) ? s_val[k] : 0.0f;
            g_tkh[0][(b * 8 + k) * TT + s] = (s == 0) ? s_tok[k] : 0;
        }
    } else {
        int nb = t & 1, ob = nb ^ 1;
        for (int i = tid; i < 8 * TT; i += 256) {
            int k = i >> 6, s = i & 63;
            int dst = (b * 8 + k) * TT + s;
            int srcrow = b * 8 + s_wk[k];
            float lp; int tk;
            if (s < t)       { lp = g_lph[ob][srcrow * TT + s]; tk = g_tkh[ob][srcrow * TT + s]; }
            else if (s == t) { lp = s_val[k]; tk = s_tok[k]; }
            else             { lp = 0.0f;     tk = 0; }
            g_lph[nb][dst] = lp; g_tkh[nb][dst] = tk;
        }
    }
}

// ---------------- 6. output ----------------
__global__ void fin_kernel(float* __restrict__ out, int n) {
    int i = blockIdx.x * blockDim.x + threadIdx.x;
    if (i >= n) return;
    if (i < NR * TT)          out[i] = g_lph[1][i];
    else if (i < 2 * NR * TT) out[i] = (float)g_tkh[1][i - NR * TT];
    else                      out[i] = 0.0f;
}

// ---------------- launch ----------------
extern "C" void kernel_launch(void* const* d_in, const int* in_sizes, int n_in,
                              void* d_out, int out_size) {
    const float* encoded   = (const float*)d_in[0];
    const float* embedding = (const float*)d_in[1];
    const float* W_ih      = (const float*)d_in[2];
    const float* W_hh      = (const float*)d_in[3];
    const float* b_ih      = (const float*)d_in[4];
    const float* b_hh      = (const float*)d_in[5];
    const float* W_out     = (const float*)d_in[6];
    const float* b_out     = (const float*)d_in[7];
    const int*   bos       = (const int*)d_in[8];
    const int*   eos       = (const int*)d_in[9];

    cudaFuncSetAttribute(logits_kernel, cudaFuncAttributeMaxDynamicSharedMemorySize, LG_SMEM);
    cudaFuncSetAttribute(gru_kernel,    cudaFuncAttributeMaxDynamicSharedMemorySize, GRU_SMEM);

    conv_kernel<<<1024, 256>>>(W_out);
    init_kernel<<<1, 32>>>(bos);

    for (int t = 0; t < TT; t++) {
        int N = (t == 0) ? BB : NR;
        gru_kernel<<<128, 256, GRU_SMEM>>>(t, N, encoded, embedding, W_ih, W_hh, b_ih, b_hh);
        logits_kernel<<<250, 128, LG_SMEM>>>(b_out);
        topk1_kernel<<<N, 256>>>();
        merge_kernel<<<BB, 256>>>(t, eos);
    }
    fin_kernel<<<(out_size + 255) / 256, 256>>>((float*)d_out, out_size);
}

// round 9
// speedup vs baseline: 2.9570x; 1.4146x over previous
#include <cuda_runtime.h>
#include <cuda_bf16.h>
#include <cstdint>
#include <float.h>
#include <math.h>

// Problem constants
#define BB 4
#define KK 8
#define VV 32000
#define EE 512
#define HH 1024
#define TT 64
#define NR 32            // B*K rows
#define NVT 250          // vocab tiles of 128
#define NCH 16           // k-chunks of 64
#define NPART 4          // topk vocab partials per row
#define PLEN (VV / NPART)

// ---------------- device scratch (static: no allocation allowed) ----------------
// packed, pre-swizzled W: [vtile][kchunk][hi|lo][128 rows x 64 cols] bf16 (16KB planes)
__device__ __nv_bfloat16 g_Wp[(size_t)NVT * NCH * 2 * 128 * 64];
// packed, pre-swizzled B (h2 hi/lo): [kchunk][hi|lo][32 rows x 64 cols]
__device__ __nv_bfloat16 g_Bp[NCH * 2 * 32 * 64];
__device__ float         g_hid[2][NR * HH];
__device__ float         g_logits[(size_t)NR * VV];
__device__ float         g_pm[NR][NPART];      // partial max
__device__ float         g_ps[NR][NPART];      // partial expsum (local max)
__device__ float         g_cv[NR][NPART][8];   // partial top-8 values (sorted)
__device__ int           g_ci[NR][NPART][8];   // partial top-8 vocab indices
__device__ float         g_prevvals[NR];
__device__ int           g_prevtok[NR];
__device__ int           g_last[NR];
__device__ int           g_which[NR];
__device__ float         g_lph[2][NR * TT];
__device__ int           g_tkh[2][NR * TT];

// ---------------- PTX helpers ----------------
__device__ __forceinline__ uint32_t smem_u32(const void* p) {
    return (uint32_t)__cvta_generic_to_shared(p);
}
__device__ __forceinline__ void mbar_init(uint32_t a, uint32_t cnt) {
    asm volatile("mbarrier.init.shared.b64 [%0], %1;" :: "r"(a), "r"(cnt) : "memory");
}
__device__ __forceinline__ void mbar_expect(uint32_t a, uint32_t tx) {
    asm volatile("mbarrier.arrive.expect_tx.shared.b64 _, [%0], %1;" :: "r"(a), "r"(tx) : "memory");
}
#define MBAR_WAIT(addr, parity) do {                                          \
    asm volatile("{\n\t.reg .pred P1;\n\t"                                    \
        "W_%=:\n\t"                                                           \
        "mbarrier.try_wait.parity.acquire.cta.shared::cta.b64 P1, [%0], %1, 0x989680;\n\t" \
        "@P1 bra D_%=;\n\t"                                                   \
        "bra W_%=;\n\t"                                                       \
        "D_%=:\n\t}"                                                          \
        :: "r"(addr), "r"(parity) : "memory"); } while (0)

__device__ __forceinline__ void bulkcp(uint32_t dst, const void* src, uint32_t bytes, uint32_t mbar) {
    asm volatile("cp.async.bulk.shared::cta.global.mbarrier::complete_tx::bytes [%0], [%1], %2, [%3];"
                 :: "r"(dst), "l"(src), "r"(bytes), "r"(mbar) : "memory");
}
__device__ __forceinline__ void ldm4(uint32_t a[4], uint32_t addr) {
    asm volatile("ldmatrix.sync.aligned.m8n8.x4.shared.b16 {%0,%1,%2,%3}, [%4];\n"
                 : "=r"(a[0]), "=r"(a[1]), "=r"(a[2]), "=r"(a[3]) : "r"(addr));
}
__device__ __forceinline__ void mma16816(float c[4], const uint32_t a[4], const uint32_t b[2]) {
    asm volatile("mma.sync.aligned.m16n8k16.row.col.f32.bf16.bf16.f32 "
                 "{%0,%1,%2,%3},{%4,%5,%6,%7},{%8,%9},{%0,%1,%2,%3};\n"
                 : "+f"(c[0]), "+f"(c[1]), "+f"(c[2]), "+f"(c[3])
                 : "r"(a[0]), "r"(a[1]), "r"(a[2]), "r"(a[3]), "r"(b[0]), "r"(b[1]));
}

// ---------------- 1. W_out -> packed pre-swizzled bf16 hi/lo ----------------
__global__ void conv_kernel(const float* __restrict__ W) {
    size_t n = (size_t)VV * HH;
    for (size_t i = (size_t)blockIdx.x * blockDim.x + threadIdx.x; i < n;
         i += (size_t)gridDim.x * blockDim.x) {
        float w = W[i];
        int v = (int)(i >> 10), k = (int)(i & 1023);
        int vt = v >> 7, row = v & 127, kc = k >> 6, col = k & 63;
        size_t base = ((size_t)vt * NCH + kc) * 2 * 8192;
        int off = (row * 128 + ((col * 2) ^ ((row & 7) << 4))) >> 1;
        __nv_bfloat16 hi = __float2bfloat16(w);
        g_Wp[base + off] = hi;
        g_Wp[base + 8192 + off] = __float2bfloat16(w - __bfloat162float(hi));
    }
}

// ---------------- 2. init ----------------
__global__ void init_kernel(const int* __restrict__ bosp) {
    int tid = threadIdx.x;
    if (tid < NR) {
        g_last[tid]     = bosp[0];
        g_prevvals[tid] = 0.0f;
        g_prevtok[tid]  = -1;
    }
}

// ---------------- 3. GRU: smem-staged x/h (transposed), warp-per-unit ----------------
#define GRU_SMEM ((512 * 33 + 1024 * 33) * 4)   // 202752 bytes

__global__ __launch_bounds__(256) void gru_kernel(
    int t, int N,
    const float* __restrict__ encoded,
    const float* __restrict__ emb,
    const float* __restrict__ Wih,
    const float* __restrict__ Whh,
    const float* __restrict__ bih,
    const float* __restrict__ bhh)
{
    extern __shared__ float sg[];
    float* sx = sg;             // [512][33]
    float* sh = sg + 512 * 33;  // [1024][33]
    int tid = threadIdx.x;

    for (int i = tid; i < N * EE; i += 256) {
        int r = i >> 9, e = i & 511;
        sx[e * 33 + r] = emb[(size_t)g_last[r] * EE + e];
    }
    for (int i = tid; i < N * HH; i += 256) {
        int r = i >> 10, e = i & 1023;
        const float* hb = (t == 0) ? (encoded + (size_t)r * HH)
                                   : (g_hid[(t - 1) & 1] + (size_t)g_which[r] * HH);
        sh[e * 33 + r] = hb[e];
    }
    __syncthreads();

    int u = blockIdx.x * 8 + (tid >> 5);
    int r = tid & 31;

    float ar = 0.f, az = 0.f, an = 0.f;
    {
        const float* w0 = Wih + (size_t)u * EE;
        const float* w1 = Wih + (size_t)(HH + u) * EE;
        const float* w2 = Wih + (size_t)(2 * HH + u) * EE;
#pragma unroll 4
        for (int e = 0; e < EE; e += 4) {
            float4 a = *reinterpret_cast<const float4*>(w0 + e);
            float4 b = *reinterpret_cast<const float4*>(w1 + e);
            float4 c = *reinterpret_cast<const float4*>(w2 + e);
            float x0 = sx[e * 33 + r], x1 = sx[(e + 1) * 33 + r];
            float x2 = sx[(e + 2) * 33 + r], x3 = sx[(e + 3) * 33 + r];
            ar += x0 * a.x + x1 * a.y + x2 * a.z + x3 * a.w;
            az += x0 * b.x + x1 * b.y + x2 * b.z + x3 * b.w;
            an += x0 * c.x + x1 * c.y + x2 * c.z + x3 * c.w;
        }
    }
    float hr = 0.f, hz = 0.f, hn = 0.f;
    {
        const float* v0 = Whh + (size_t)u * HH;
        const float* v1 = Whh + (size_t)(HH + u) * HH;
        const float* v2 = Whh + (size_t)(2 * HH + u) * HH;
#pragma unroll 4
        for (int e = 0; e < HH; e += 4) {
            float4 a = *reinterpret_cast<const float4*>(v0 + e);
            float4 b = *reinterpret_cast<const float4*>(v1 + e);
            float4 c = *reinterpret_cast<const float4*>(v2 + e);
            float h0 = sh[e * 33 + r], h1 = sh[(e + 1) * 33 + r];
            float h2v = sh[(e + 2) * 33 + r], h3 = sh[(e + 3) * 33 + r];
            hr += h0 * a.x + h1 * a.y + h2v * a.z + h3 * a.w;
            hz += h0 * b.x + h1 * b.y + h2v * b.z + h3 * b.w;
            hn += h0 * c.x + h1 * c.y + h2v * c.z + h3 * c.w;
        }
    }
    if (r < N) {
        float rg = 1.0f / (1.0f + expf(-(ar + hr + bih[u] + bhh[u])));
        float zg = 1.0f / (1.0f + expf(-(az + hz + bih[HH + u] + bhh[HH + u])));
        float ng = tanhf(an + bih[2 * HH + u] + rg * (hn + bhh[2 * HH + u]));
        float h2 = (1.0f - zg) * ng + zg * sh[u * 33 + r];

        g_hid[t & 1][r * HH + u] = h2;
        // pre-swizzled packed B write
        int kc = u >> 6, col = u & 63;
        int off = (r * 128 + ((col * 2) ^ ((r & 7) << 4))) >> 1;
        __nv_bfloat16 hi = __float2bfloat16(h2);
        g_Bp[(kc * 2 + 0) * 2048 + off] = hi;
        g_Bp[(kc * 2 + 1) * 2048 + off] = __float2bfloat16(h2 - __bfloat162float(hi));
    }
}

// ---------------- 4. logits GEMM: split-bf16 tensor core, bulk-copy 2-stage ring ----------------
#define STB 40960                     // per-stage bytes: A 32KB (hi+lo) + B 8KB (hi+lo)
#define LG_SMEM (2 * STB + 16)        // + 2 mbarriers

__global__ __launch_bounds__(128) void logits_kernel(const float* __restrict__ b_out) {
    extern __shared__ char smem[];
    uint32_t sbase = smem_u32(smem);
    uint32_t mbar = sbase + 2 * STB;
    int tid = threadIdx.x, warp = tid >> 5, lane = tid & 31;
    int v0 = blockIdx.x * 128;

    if (tid == 0) { mbar_init(mbar, 1); mbar_init(mbar + 8, 1); }
    __syncthreads();
    if (tid == 0) {
#pragma unroll
        for (int kc = 0; kc < 2; kc++) {
            mbar_expect(mbar + kc * 8, STB);
            bulkcp(sbase + kc * STB,
                   (const char*)g_Wp + ((size_t)blockIdx.x * NCH + kc) * 32768, 32768,
                   mbar + kc * 8);
            bulkcp(sbase + kc * STB + 32768,
                   (const char*)g_Bp + kc * 8192, 8192, mbar + kc * 8);
        }
    }

    float acc[2][4][4];
#pragma unroll
    for (int m = 0; m < 2; m++)
#pragma unroll
        for (int n = 0; n < 4; n++)
#pragma unroll
            for (int f = 0; f < 4; f++) acc[m][n][f] = 0.0f;

    for (int kc = 0; kc < NCH; kc++) {
        int st = kc & 1;
        MBAR_WAIT(mbar + st * 8, (kc >> 1) & 1);
        uint32_t aA = sbase + st * STB;
        const char* pB = smem + st * STB + 32768;

#pragma unroll
        for (int kk = 0; kk < 4; kk++) {
            int kb = kk * 16;
            uint32_t ahi[2][4], alo[2][4];
#pragma unroll
            for (int mt = 0; mt < 2; mt++) {
                int row = warp * 32 + mt * 16 + (lane & 15);
                int colByte = (kb + ((lane >> 4) << 3)) * 2;
                uint32_t off = row * 128 + (colByte ^ ((row & 7) << 4));
                ldm4(ahi[mt], aA + off);
                ldm4(alo[mt], aA + 16384 + off);
            }
            uint32_t bhi[4][2], blo[4][2];
#pragma unroll
            for (int nt = 0; nt < 4; nt++) {
                int n = nt * 8 + (lane >> 2);
                int c0 = (kb + ((lane & 3) << 1)) * 2;
                uint32_t x = (n & 7) << 4;
                uint32_t o0 = n * 128 + (c0 ^ x);
                uint32_t o1 = n * 128 + ((c0 + 16) ^ x);
                bhi[nt][0] = *(const uint32_t*)(pB + o0);
                bhi[nt][1] = *(const uint32_t*)(pB + o1);
                blo[nt][0] = *(const uint32_t*)(pB + 4096 + o0);
                blo[nt][1] = *(const uint32_t*)(pB + 4096 + o1);
            }
#pragma unroll
            for (int mt = 0; mt < 2; mt++)
#pragma unroll
                for (int nt = 0; nt < 4; nt++) {
                    mma16816(acc[mt][nt], ahi[mt], bhi[nt]);
                    mma16816(acc[mt][nt], ahi[mt], blo[nt]);
                    mma16816(acc[mt][nt], alo[mt], bhi[nt]);
                }
        }
        __syncthreads();
        if (tid == 0 && kc + 2 < NCH) {
            mbar_expect(mbar + st * 8, STB);
            bulkcp(sbase + st * STB,
                   (const char*)g_Wp + ((size_t)blockIdx.x * NCH + kc + 2) * 32768, 32768,
                   mbar + st * 8);
            bulkcp(sbase + st * STB + 32768,
                   (const char*)g_Bp + (kc + 2) * 8192, 8192, mbar + st * 8);
        }
    }

    // epilogue: transpose through smem, coalesced store with bias
    float* sOut = (float*)smem;   // [32][132]
#pragma unroll
    for (int mt = 0; mt < 2; mt++)
#pragma unroll
        for (int nt = 0; nt < 4; nt++) {
            int vl = warp * 32 + mt * 16 + (lane >> 2);
            int n0 = nt * 8 + ((lane & 3) << 1);
            sOut[n0 * 132 + vl]           = acc[mt][nt][0];
            sOut[(n0 + 1) * 132 + vl]     = acc[mt][nt][1];
            sOut[n0 * 132 + vl + 8]       = acc[mt][nt][2];
            sOut[(n0 + 1) * 132 + vl + 8] = acc[mt][nt][3];
        }
    __syncthreads();
#pragma unroll
    for (int i = tid; i < 32 * 128; i += 128) {
        int n = i >> 7, vl = i & 127;
        g_logits[(size_t)n * VV + v0 + vl] = sOut[n * 132 + vl] + b_out[v0 + vl];
    }
}

// ---------------- 5. top-k machinery ----------------
__device__ __forceinline__ bool betterf(float va, int ia, float vb, int ib) {
    return (va > vb) || (va == vb && ia < ib);   // JAX tie-break: lower flat index
}

#define INS_DECL float lv[8]; int li[8]; \
    _Pragma("unroll") for (int j = 0; j < 8; j++) { lv[j] = -FLT_MAX; li[j] = 0x7FFFFFFF; }

#define INS(vx, ix) do { float _v = (vx); int _i = (ix); \
    if (betterf(_v, _i, lv[7], li[7])) { \
        bool placed = false; \
        _Pragma("unroll") for (int j = 7; j >= 1; j--) { \
            if (!placed) { \
                if (betterf(_v, _i, lv[j-1], li[j-1])) { lv[j] = lv[j-1]; li[j] = li[j-1]; } \
                else { lv[j] = _v; li[j] = _i; placed = true; } } } \
        if (!placed) { lv[0] = _v; li[0] = _i; } } } while (0)

// pairwise merge of sorted-8 lists in smem, lists at sv[tid*8]
__device__ __forceinline__ void merge_lists(float* sv, int* si, int tid, int nfirst) {
    for (int off = nfirst; off >= 1; off >>= 1) {
        if (tid < off) {
            int pa = tid * 8, pb = (tid + off) * 8;
            float rv[8]; int ri[8];
            int ia = 0, ib = 0;
#pragma unroll
            for (int j = 0; j < 8; j++) {
                float va = sv[pa + ia], vb = sv[pb + ib];
                int   xa = si[pa + ia], xb = si[pb + ib];
                bool ta = betterf(va, xa, vb, xb);
                rv[j] = ta ? va : vb; ri[j] = ta ? xa : xb;
                ia += ta; ib += !ta;
            }
#pragma unroll
            for (int j = 0; j < 8; j++) { sv[pa + j] = rv[j]; si[pa + j] = ri[j]; }
        }
        __syncthreads();
    }
}

// phase 1: per (row, vocab-partial): partial max, expsum, top-8. grid = N*NPART.
__global__ __launch_bounds__(256) void topk1_kernel() {
    __shared__ float red[256];
    __shared__ float sv[2048]; __shared__ int si[2048];
    int r = blockIdx.x >> 2, p = blockIdx.x & 3;
    int tid = threadIdx.x;
    const float4* lg4 = (const float4*)(g_logits + (size_t)r * VV + p * PLEN);

    float m = -FLT_MAX;
    INS_DECL
#pragma unroll 2
    for (int i = tid; i < PLEN / 4; i += 256) {
        float4 x = lg4[i];
        int v = p * PLEN + i * 4;
        m = fmaxf(m, fmaxf(fmaxf(x.x, x.y), fmaxf(x.z, x.w)));
        INS(x.x, v); INS(x.y, v + 1); INS(x.z, v + 2); INS(x.w, v + 3);
    }
    red[tid] = m; __syncthreads();
    for (int o = 128; o > 0; o >>= 1) { if (tid < o) red[tid] = fmaxf(red[tid], red[tid + o]); __syncthreads(); }
    m = red[0]; __syncthreads();

    float s = 0.f;
#pragma unroll 2
    for (int i = tid; i < PLEN / 4; i += 256) {
        float4 x = lg4[i];
        s += __expf(x.x - m) + __expf(x.y - m) + __expf(x.z - m) + __expf(x.w - m);
    }
    red[tid] = s; __syncthreads();
    for (int o = 128; o > 0; o >>= 1) { if (tid < o) red[tid] += red[tid + o]; __syncthreads(); }
    if (tid == 0) { g_pm[r][p] = m; g_ps[r][p] = red[0]; }

#pragma unroll
    for (int j = 0; j < 8; j++) { sv[tid * 8 + j] = lv[j]; si[tid * 8 + j] = li[j]; }
    __syncthreads();
    merge_lists(sv, si, tid, 128);
    if (tid < 8) { g_cv[r][p][tid] = sv[tid]; g_ci[r][p][tid] = si[tid]; }
}

// phase 2: per-batch LSE combine + 32-list merge + beam update + history gather
__global__ __launch_bounds__(64) void merge_kernel(int t, const int* __restrict__ eosp) {
    __shared__ float sv[256]; __shared__ int si[256];
    __shared__ float s_rc[8];
    __shared__ float s_val[8]; __shared__ int s_tok[8], s_wk[8];
    int b = blockIdx.x, tid = threadIdx.x;
    int eos = eosp[0];

    if (t == 0) {
        if (tid == 0) {
            float M = -FLT_MAX;
#pragma unroll
            for (int p = 0; p < NPART; p++) M = fmaxf(M, g_pm[b][p]);
            float S = 0.f;
#pragma unroll
            for (int p = 0; p < NPART; p++) S += g_ps[b][p] * __expf(g_pm[b][p] - M);
            s_rc[0] = -(M + logf(S));
        }
    } else if (tid < 8) {
        int row = b * 8 + tid;
        float M = -FLT_MAX;
#pragma unroll
        for (int p = 0; p < NPART; p++) M = fmaxf(M, g_pm[row][p]);
        float S = 0.f;
#pragma unroll
        for (int p = 0; p < NPART; p++) S += g_ps[row][p] * __expf(g_pm[row][p] - M);
        s_rc[tid] = g_prevvals[row] - (M + logf(S));
    }
    __syncthreads();

    if (tid < 32) {
        if (t == 0) {
            if (tid < NPART) {
#pragma unroll
                for (int j = 0; j < 8; j++) {
                    sv[tid * 8 + j] = g_cv[b][tid][j] + s_rc[0];
                    si[tid * 8 + j] = g_ci[b][tid][j];
                }
            } else {
#pragma unroll
                for (int j = 0; j < 8; j++) { sv[tid * 8 + j] = -FLT_MAX; si[tid * 8 + j] = 0x7FFFFFFF; }
            }
        } else {
            int k = tid >> 2, p = tid & 3, row = b * 8 + k;
            if (g_prevtok[row] == eos) {
#pragma unroll
                for (int j = 0; j < 8; j++) {
                    bool real = (p == 0 && j == 0);
                    sv[tid * 8 + j] = real ? 0.0f : -FLT_MAX;
                    si[tid * 8 + j] = real ? (k * VV + eos) : 0x7FFFFFFF;
                }
            } else {
                float rc = s_rc[k];
#pragma unroll
                for (int j = 0; j < 8; j++) {
                    sv[tid * 8 + j] = g_cv[row][p][j] + rc;
                    si[tid * 8 + j] = k * VV + g_ci[row][p][j];
                }
            }
        }
    }
    __syncthreads();
    merge_lists(sv, si, tid, 16);

    if (tid < 8) {
        float v = sv[tid]; int id = si[tid];
        int tok = (t == 0) ? id : (id % VV);
        int wk  = (t == 0) ? 0  : (id / VV);
        s_val[tid] = v; s_tok[tid] = tok; s_wk[tid] = wk;
        int row = b * 8 + tid;
        g_prevvals[row] = v; g_prevtok[row] = tok; g_last[row] = tok;
        g_which[row] = (t == 0) ? b : (b * 8 + wk);
    }
    __syncthreads();

    if (t == 0) {
        for (int i = tid; i < 8 * TT; i += 64) {
            int k = i >> 6, s = i & 63;
            g_lph[0][(b * 8 + k) * TT + s] = (s == 0) ? s_val[k] : 0.0f;
            g_tkh[0][(b * 8 + k) * TT + s] = (s == 0) ? s_tok[k] : 0;
        }
    } else {
        int nb = t & 1, ob = nb ^ 1;
        for (int i = tid; i < 8 * TT; i += 64) {
            int k = i >> 6, s = i & 63;
            int dst = (b * 8 + k) * TT + s;
            int srcrow = b * 8 + s_wk[k];
            float lp; int tk;
            if (s < t)       { lp = g_lph[ob][srcrow * TT + s]; tk = g_tkh[ob][srcrow * TT + s]; }
            else if (s == t) { lp = s_val[k]; tk = s_tok[k]; }
            else             { lp = 0.0f;     tk = 0; }
            g_lph[nb][dst] = lp; g_tkh[nb][dst] = tk;
        }
    }
}

// ---------------- 6. output ----------------
__global__ void fin_kernel(float* __restrict__ out, int n) {
    int i = blockIdx.x * blockDim.x + threadIdx.x;
    if (i >= n) return;
    if (i < NR * TT)          out[i] = g_lph[1][i];
    else if (i < 2 * NR * TT) out[i] = (float)g_tkh[1][i - NR * TT];
    else                      out[i] = 0.0f;
}

// ---------------- launch ----------------
extern "C" void kernel_launch(void* const* d_in, const int* in_sizes, int n_in,
                              void* d_out, int out_size) {
    const float* encoded   = (const float*)d_in[0];
    const float* embedding = (const float*)d_in[1];
    const float* W_ih      = (const float*)d_in[2];
    const float* W_hh      = (const float*)d_in[3];
    const float* b_ih      = (const float*)d_in[4];
    const float* b_hh      = (const float*)d_in[5];
    const float* W_out     = (const float*)d_in[6];
    const float* b_out     = (const float*)d_in[7];
    const int*   bos       = (const int*)d_in[8];
    const int*   eos       = (const int*)d_in[9];

    cudaFuncSetAttribute(logits_kernel, cudaFuncAttributeMaxDynamicSharedMemorySize, LG_SMEM);
    cudaFuncSetAttribute(gru_kernel,    cudaFuncAttributeMaxDynamicSharedMemorySize, GRU_SMEM);

    conv_kernel<<<1024, 256>>>(W_out);
    init_kernel<<<1, 32>>>(bos);

    for (int t = 0; t < TT; t++) {
        int N = (t == 0) ? BB : NR;
        gru_kernel<<<128, 256, GRU_SMEM>>>(t, N, encoded, embedding, W_ih, W_hh, b_ih, b_hh);
        logits_kernel<<<NVT, 128, LG_SMEM>>>(b_out);
        topk1_kernel<<<N * NPART, 256>>>();
        merge_kernel<<<BB, 64>>>(t, eos);
    }
    fin_kernel<<<(out_size + 255) / 256, 256>>>((float*)d_out, out_size);
}

// round 10
// speedup vs baseline: 5.4660x; 1.8485x over previous
#include <cuda_runtime.h>
#include <cuda_bf16.h>
#include <cstdint>
#include <float.h>
#include <math.h>

// Problem constants
#define BB 4
#define KK 8
#define VV 32000
#define EE 512
#define HH 1024
#define TT 64
#define NR 32            // B*K rows
#define NVT 250          // vocab tiles of 128
#define NCH 16           // k-chunks of 64 (logits)

// ---------------- device scratch (static: no allocation allowed) ----------------
// packed, pre-swizzled W_out: [vtile][kchunk][hi|lo][128 x 64] bf16
__device__ __align__(128) __nv_bfloat16 g_Wp[(size_t)NVT * NCH * 2 * 8192];
// packed, pre-swizzled W_ih: [mtile 24][kchunk 8][hi|lo][128 x 64]
__device__ __align__(128) __nv_bfloat16 g_Pih[(size_t)24 * 8 * 2 * 8192];
// packed, pre-swizzled W_hh: [mtile 24][kchunk 16][hi|lo][128 x 64]
__device__ __align__(128) __nv_bfloat16 g_Phh[(size_t)24 * 16 * 2 * 8192];
// packed B operands (32 x 64 per chunk, hi|lo)
__device__ __align__(128) __nv_bfloat16 g_Bp[NCH * 2 * 2048];   // h2 (for logits)
__device__ __align__(128) __nv_bfloat16 g_Xp[8 * 2 * 2048];     // emb(x) for GRU
__device__ __align__(128) __nv_bfloat16 g_Hp[16 * 2 * 2048];    // h_prev for GRU
// GRU GEMM partials (split-K)
__device__ float g_pih[2][NR][3072];
__device__ float g_phh[4][NR][3072];
// logits per-(row, vtile) stats
__device__ float g_pvm[NR][NVT];
__device__ float g_pvs[NR][NVT];
__device__ float g_p8v[NR][NVT][8];
__device__ int   g_p8i[NR][NVT][8];
// beam state
__device__ float g_hid[2][NR * HH];
__device__ float g_prevvals[NR];
__device__ int   g_prevtok[NR];
__device__ int   g_last[NR];
__device__ int   g_which[NR];
__device__ float g_lph[2][NR * TT];
__device__ int   g_tkh[2][NR * TT];

// ---------------- PTX helpers ----------------
__device__ __forceinline__ uint32_t smem_u32(const void* p) {
    return (uint32_t)__cvta_generic_to_shared(p);
}
__device__ __forceinline__ void mbar_init(uint32_t a, uint32_t cnt) {
    asm volatile("mbarrier.init.shared.b64 [%0], %1;" :: "r"(a), "r"(cnt) : "memory");
}
__device__ __forceinline__ void mbar_expect(uint32_t a, uint32_t tx) {
    asm volatile("mbarrier.arrive.expect_tx.shared.b64 _, [%0], %1;" :: "r"(a), "r"(tx) : "memory");
}
#define MBAR_WAIT(addr, parity) do {                                          \
    asm volatile("{\n\t.reg .pred P1;\n\t"                                    \
        "W_%=:\n\t"                                                           \
        "mbarrier.try_wait.parity.acquire.cta.shared::cta.b64 P1, [%0], %1, 0x989680;\n\t" \
        "@P1 bra D_%=;\n\t"                                                   \
        "bra W_%=;\n\t"                                                       \
        "D_%=:\n\t}"                                                          \
        :: "r"(addr), "r"(parity) : "memory"); } while (0)

__device__ __forceinline__ void bulkcp(uint32_t dst, const void* src, uint32_t bytes, uint32_t mbar) {
    asm volatile("cp.async.bulk.shared::cta.global.mbarrier::complete_tx::bytes [%0], [%1], %2, [%3];"
                 :: "r"(dst), "l"(src), "r"(bytes), "r"(mbar) : "memory");
}
__device__ __forceinline__ void ldm4(uint32_t a[4], uint32_t addr) {
    asm volatile("ldmatrix.sync.aligned.m8n8.x4.shared.b16 {%0,%1,%2,%3}, [%4];\n"
                 : "=r"(a[0]), "=r"(a[1]), "=r"(a[2]), "=r"(a[3]) : "r"(addr));
}
__device__ __forceinline__ void mma16816(float c[4], const uint32_t a[4], const uint32_t b[2]) {
    asm volatile("mma.sync.aligned.m16n8k16.row.col.f32.bf16.bf16.f32 "
                 "{%0,%1,%2,%3},{%4,%5,%6,%7},{%8,%9},{%0,%1,%2,%3};\n"
                 : "+f"(c[0]), "+f"(c[1]), "+f"(c[2]), "+f"(c[3])
                 : "r"(a[0]), "r"(a[1]), "r"(a[2]), "r"(a[3]), "r"(b[0]), "r"(b[1]));
}

// swizzled offset (elements) inside a [rows x 64] bf16 plane
__device__ __forceinline__ int swz(int row, int col) {
    return (row * 128 + ((col * 2) ^ ((row & 7) << 4))) >> 1;
}

// ---------------- weight pack kernels (run each launch, pre-loop) ----------------
__global__ void conv_kernel(const float* __restrict__ W) {   // W_out
    size_t n = (size_t)VV * HH;
    for (size_t i = (size_t)blockIdx.x * blockDim.x + threadIdx.x; i < n;
         i += (size_t)gridDim.x * blockDim.x) {
        float w = W[i];
        int v = (int)(i >> 10), k = (int)(i & 1023);
        int vt = v >> 7, row = v & 127, kc = k >> 6, col = k & 63;
        size_t base = ((size_t)vt * NCH + kc) * 2 * 8192;
        int off = swz(row, col);
        __nv_bfloat16 hi = __float2bfloat16(w);
        g_Wp[base + off] = hi;
        g_Wp[base + 8192 + off] = __float2bfloat16(w - __bfloat162float(hi));
    }
}
__global__ void wpack_ih_kernel(const float* __restrict__ W) {  // [3072 x 512]
    size_t n = (size_t)3072 * 512;
    for (size_t i = (size_t)blockIdx.x * blockDim.x + threadIdx.x; i < n;
         i += (size_t)gridDim.x * blockDim.x) {
        float w = W[i];
        int v = (int)(i >> 9), k = (int)(i & 511);
        int mt = v >> 7, row = v & 127, kc = k >> 6, col = k & 63;
        size_t base = ((size_t)mt * 8 + kc) * 2 * 8192;
        int off = swz(row, col);
        __nv_bfloat16 hi = __float2bfloat16(w);
        g_Pih[base + off] = hi;
        g_Pih[base + 8192 + off] = __float2bfloat16(w - __bfloat162float(hi));
    }
}
__global__ void wpack_hh_kernel(const float* __restrict__ W) {  // [3072 x 1024]
    size_t n = (size_t)3072 * 1024;
    for (size_t i = (size_t)blockIdx.x * blockDim.x + threadIdx.x; i < n;
         i += (size_t)gridDim.x * blockDim.x) {
        float w = W[i];
        int v = (int)(i >> 10), k = (int)(i & 1023);
        int mt = v >> 7, row = v & 127, kc = k >> 6, col = k & 63;
        size_t base = ((size_t)mt * 16 + kc) * 2 * 8192;
        int off = swz(row, col);
        __nv_bfloat16 hi = __float2bfloat16(w);
        g_Phh[base + off] = hi;
        g_Phh[base + 8192 + off] = __float2bfloat16(w - __bfloat162float(hi));
    }
}

__global__ void init_kernel(const int* __restrict__ bosp) {
    int tid = threadIdx.x;
    if (tid < NR) {
        g_last[tid]     = bosp[0];
        g_prevvals[tid] = 0.0f;
        g_prevtok[tid]  = -1;
    }
}

// ---------------- per-step 1: pack x (emb gather) and h_prev (beam gather) ----------------
__global__ __launch_bounds__(256) void pack_kernel(int t,
        const float* __restrict__ encoded, const float* __restrict__ emb) {
    for (int idx = blockIdx.x * 256 + threadIdx.x; idx < NR * (EE + HH); idx += 32 * 256) {
        if (idx < NR * EE) {
            int r = idx >> 9, e = idx & 511;
            float v = emb[(size_t)g_last[r] * EE + e];
            int kc = e >> 6, col = e & 63;
            int off = swz(r, col);
            __nv_bfloat16 hi = __float2bfloat16(v);
            g_Xp[(kc * 2 + 0) * 2048 + off] = hi;
            g_Xp[(kc * 2 + 1) * 2048 + off] = __float2bfloat16(v - __bfloat162float(hi));
        } else {
            int j = idx - NR * EE;
            int r = j >> 10, e = j & 1023;
            float v = (t == 0) ? encoded[(size_t)((r < BB) ? r : 0) * HH + e]
                               : g_hid[(t - 1) & 1][(size_t)g_which[r] * HH + e];
            int kc = e >> 6, col = e & 63;
            int off = swz(r, col);
            __nv_bfloat16 hi = __float2bfloat16(v);
            g_Hp[(kc * 2 + 0) * 2048 + off] = hi;
            g_Hp[(kc * 2 + 1) * 2048 + off] = __float2bfloat16(v - __bfloat162float(hi));
        }
    }
}

// ---------------- per-step 2: GRU GEMMs (split-bf16 TC, split-K) ----------------
#define STB 40960                     // per-stage bytes: A 32KB + B 8KB
#define GG_SMEM (2 * STB + 16)

__global__ __launch_bounds__(128) void grugemm_kernel() {
    extern __shared__ char smem[];
    uint32_t sbase = smem_u32(smem);
    uint32_t mbar = sbase + 2 * STB;
    int tid = threadIdx.x, warp = tid >> 5, lane = tid & 31;
    int bid = blockIdx.x;

    const __nv_bfloat16* Abase;
    const __nv_bfloat16* Bbase;
    float* outp;
    int mtile;
    if (bid < 48) {                               // W_ih tiles: 24 mtiles x 2 K-splits
        mtile = bid >> 1; int split = bid & 1;
        Abase = g_Pih + ((size_t)(mtile * 8 + split * 4)) * 16384;
        Bbase = g_Xp + (size_t)(split * 4) * 4096;
        outp  = &g_pih[split][0][0];
    } else {                                      // W_hh tiles: 24 mtiles x 4 K-splits
        int q = bid - 48;
        mtile = q >> 2; int split = q & 3;
        Abase = g_Phh + ((size_t)(mtile * 16 + split * 4)) * 16384;
        Bbase = g_Hp + (size_t)(split * 4) * 4096;
        outp  = &g_phh[split][0][0];
    }

    if (tid == 0) { mbar_init(mbar, 1); mbar_init(mbar + 8, 1); }
    __syncthreads();
    if (tid == 0) {
#pragma unroll
        for (int kc = 0; kc < 2; kc++) {
            mbar_expect(mbar + kc * 8, STB);
            bulkcp(sbase + kc * STB, (const char*)Abase + (size_t)kc * 32768, 32768, mbar + kc * 8);
            bulkcp(sbase + kc * STB + 32768, (const char*)Bbase + (size_t)kc * 8192, 8192, mbar + kc * 8);
        }
    }

    float acc[2][4][4];
#pragma unroll
    for (int m = 0; m < 2; m++)
#pragma unroll
        for (int n = 0; n < 4; n++)
#pragma unroll
            for (int f = 0; f < 4; f++) acc[m][n][f] = 0.0f;

    for (int kc = 0; kc < 4; kc++) {
        int st = kc & 1;
        MBAR_WAIT(mbar + st * 8, (kc >> 1) & 1);
        uint32_t aA = sbase + st * STB;
        const char* pB = smem + st * STB + 32768;

#pragma unroll
        for (int kk = 0; kk < 4; kk++) {
            int kb = kk * 16;
            uint32_t ahi[2][4], alo[2][4];
#pragma unroll
            for (int mt = 0; mt < 2; mt++) {
                int row = warp * 32 + mt * 16 + (lane & 15);
                int colByte = (kb + ((lane >> 4) << 3)) * 2;
                uint32_t off = row * 128 + (colByte ^ ((row & 7) << 4));
                ldm4(ahi[mt], aA + off);
                ldm4(alo[mt], aA + 16384 + off);
            }
            uint32_t bhi[4][2], blo[4][2];
#pragma unroll
            for (int nt = 0; nt < 4; nt++) {
                int n = nt * 8 + (lane >> 2);
                int c0 = (kb + ((lane & 3) << 1)) * 2;
                uint32_t x = (n & 7) << 4;
                uint32_t o0 = n * 128 + (c0 ^ x);
                uint32_t o1 = n * 128 + ((c0 + 16) ^ x);
                bhi[nt][0] = *(const uint32_t*)(pB + o0);
                bhi[nt][1] = *(const uint32_t*)(pB + o1);
                blo[nt][0] = *(const uint32_t*)(pB + 4096 + o0);
                blo[nt][1] = *(const uint32_t*)(pB + 4096 + o1);
            }
#pragma unroll
            for (int mt = 0; mt < 2; mt++)
#pragma unroll
                for (int nt = 0; nt < 4; nt++) {
                    mma16816(acc[mt][nt], ahi[mt], bhi[nt]);
                    mma16816(acc[mt][nt], ahi[mt], blo[nt]);
                    mma16816(acc[mt][nt], alo[mt], bhi[nt]);
                }
        }
        __syncthreads();
        if (tid == 0 && kc + 2 < 4) {
            mbar_expect(mbar + st * 8, STB);
            bulkcp(sbase + st * STB, (const char*)Abase + (size_t)(kc + 2) * 32768, 32768, mbar + st * 8);
            bulkcp(sbase + st * STB + 32768, (const char*)Bbase + (size_t)(kc + 2) * 8192, 8192, mbar + st * 8);
        }
    }

    float* sOut = (float*)smem;   // [32][132]
#pragma unroll
    for (int mt = 0; mt < 2; mt++)
#pragma unroll
        for (int nt = 0; nt < 4; nt++) {
            int vl = warp * 32 + mt * 16 + (lane >> 2);
            int n0 = nt * 8 + ((lane & 3) << 1);
            sOut[n0 * 132 + vl]           = acc[mt][nt][0];
            sOut[(n0 + 1) * 132 + vl]     = acc[mt][nt][1];
            sOut[n0 * 132 + vl + 8]       = acc[mt][nt][2];
            sOut[(n0 + 1) * 132 + vl + 8] = acc[mt][nt][3];
        }
    __syncthreads();
#pragma unroll
    for (int i = tid; i < 32 * 128; i += 128) {
        int n = i >> 7, m = i & 127;
        outp[(size_t)n * 3072 + mtile * 128 + m] = sOut[n * 132 + m];
    }
}

// ---------------- per-step 3: GRU elementwise (gates, h2, B-pack) ----------------
__global__ __launch_bounds__(256) void gruelem_kernel(int t,
        const float* __restrict__ encoded,
        const float* __restrict__ bih, const float* __restrict__ bhh) {
    int idx = blockIdx.x * 256 + threadIdx.x;   // < 32768
    int r = idx >> 10, u = idx & 1023;

    float gir = g_pih[0][r][u]        + g_pih[1][r][u];
    float giz = g_pih[0][r][1024 + u] + g_pih[1][r][1024 + u];
    float gin = g_pih[0][r][2048 + u] + g_pih[1][r][2048 + u];
    float ghr = g_phh[0][r][u] + g_phh[1][r][u] + g_phh[2][r][u] + g_phh[3][r][u];
    float ghz = g_phh[0][r][1024 + u] + g_phh[1][r][1024 + u] + g_phh[2][r][1024 + u] + g_phh[3][r][1024 + u];
    float ghn = g_phh[0][r][2048 + u] + g_phh[1][r][2048 + u] + g_phh[2][r][2048 + u] + g_phh[3][r][2048 + u];

    float hprev = (t == 0) ? encoded[(size_t)((r < BB) ? r : 0) * HH + u]
                           : g_hid[(t - 1) & 1][(size_t)g_which[r] * HH + u];

    float rg = 1.0f / (1.0f + expf(-(gir + ghr + bih[u] + bhh[u])));
    float zg = 1.0f / (1.0f + expf(-(giz + ghz + bih[1024 + u] + bhh[1024 + u])));
    float ng = tanhf(gin + bih[2048 + u] + rg * (ghn + bhh[2048 + u]));
    float h2 = (1.0f - zg) * ng + zg * hprev;

    g_hid[t & 1][r * HH + u] = h2;
    int kc = u >> 6, col = u & 63;
    int off = swz(r, col);
    __nv_bfloat16 hi = __float2bfloat16(h2);
    g_Bp[(kc * 2 + 0) * 2048 + off] = hi;
    g_Bp[(kc * 2 + 1) * 2048 + off] = __float2bfloat16(h2 - __bfloat162float(hi));
}

// ---------------- top-k primitives ----------------
__device__ __forceinline__ bool betterf(float va, int ia, float vb, int ib) {
    return (va > vb) || (va == vb && ia < ib);
}
#define INS_DECL float lv[8]; int li[8]; \
    _Pragma("unroll") for (int j = 0; j < 8; j++) { lv[j] = -FLT_MAX; li[j] = 0x7FFFFFFF; }
#define INS(vx, ix) do { float _v = (vx); int _i = (ix); \
    if (betterf(_v, _i, lv[7], li[7])) { \
        bool placed = false; \
        _Pragma("unroll") for (int j = 7; j >= 1; j--) { \
            if (!placed) { \
                if (betterf(_v, _i, lv[j-1], li[j-1])) { lv[j] = lv[j-1]; li[j] = li[j-1]; } \
                else { lv[j] = _v; li[j] = _i; placed = true; } } } \
        if (!placed) { lv[0] = _v; li[0] = _i; } } } while (0)

__device__ __forceinline__ void merge_pair(float* sv, int* si, int pa, int pb) {
    float rv[8]; int ri[8]; int ia = 0, ib = 0;
#pragma unroll
    for (int j = 0; j < 8; j++) {
        float va = sv[pa + ia], vb = sv[pb + ib];
        int   xa = si[pa + ia], xb = si[pb + ib];
        bool ta = betterf(va, xa, vb, xb);
        rv[j] = ta ? va : vb; ri[j] = ta ? xa : xb;
        ia += ta; ib += !ta;
    }
#pragma unroll
    for (int j = 0; j < 8; j++) { sv[pa + j] = rv[j]; si[pa + j] = ri[j]; }
}
__device__ __forceinline__ void merge_lists(float* sv, int* si, int tid, int nfirst) {
    for (int off = nfirst; off >= 1; off >>= 1) {
        if (tid < off) merge_pair(sv, si, tid * 8, (tid + off) * 8);
        __syncthreads();
    }
}

// ---------------- per-step 4: logits GEMM + fused per-vtile stats ----------------
#define LG_SMEM (2 * STB + 16)

__global__ __launch_bounds__(128) void logits_kernel(const float* __restrict__ b_out) {
    extern __shared__ char smem[];
    uint32_t sbase = smem_u32(smem);
    uint32_t mbar = sbase + 2 * STB;
    int tid = threadIdx.x, warp = tid >> 5, lane = tid & 31;
    int v0 = blockIdx.x * 128;

    if (tid == 0) { mbar_init(mbar, 1); mbar_init(mbar + 8, 1); }
    __syncthreads();
    if (tid == 0) {
#pragma unroll
        for (int kc = 0; kc < 2; kc++) {
            mbar_expect(mbar + kc * 8, STB);
            bulkcp(sbase + kc * STB,
                   (const char*)g_Wp + ((size_t)blockIdx.x * NCH + kc) * 32768, 32768,
                   mbar + kc * 8);
            bulkcp(sbase + kc * STB + 32768, (const char*)g_Bp + kc * 8192, 8192, mbar + kc * 8);
        }
    }

    float acc[2][4][4];
#pragma unroll
    for (int m = 0; m < 2; m++)
#pragma unroll
        for (int n = 0; n < 4; n++)
#pragma unroll
            for (int f = 0; f < 4; f++) acc[m][n][f] = 0.0f;

    for (int kc = 0; kc < NCH; kc++) {
        int st = kc & 1;
        MBAR_WAIT(mbar + st * 8, (kc >> 1) & 1);
        uint32_t aA = sbase + st * STB;
        const char* pB = smem + st * STB + 32768;

#pragma unroll
        for (int kk = 0; kk < 4; kk++) {
            int kb = kk * 16;
            uint32_t ahi[2][4], alo[2][4];
#pragma unroll
            for (int mt = 0; mt < 2; mt++) {
                int row = warp * 32 + mt * 16 + (lane & 15);
                int colByte = (kb + ((lane >> 4) << 3)) * 2;
                uint32_t off = row * 128 + (colByte ^ ((row & 7) << 4));
                ldm4(ahi[mt], aA + off);
                ldm4(alo[mt], aA + 16384 + off);
            }
            uint32_t bhi[4][2], blo[4][2];
#pragma unroll
            for (int nt = 0; nt < 4; nt++) {
                int n = nt * 8 + (lane >> 2);
                int c0 = (kb + ((lane & 3) << 1)) * 2;
                uint32_t x = (n & 7) << 4;
                uint32_t o0 = n * 128 + (c0 ^ x);
                uint32_t o1 = n * 128 + ((c0 + 16) ^ x);
                bhi[nt][0] = *(const uint32_t*)(pB + o0);
                bhi[nt][1] = *(const uint32_t*)(pB + o1);
                blo[nt][0] = *(const uint32_t*)(pB + 4096 + o0);
                blo[nt][1] = *(const uint32_t*)(pB + 4096 + o1);
            }
#pragma unroll
            for (int mt = 0; mt < 2; mt++)
#pragma unroll
                for (int nt = 0; nt < 4; nt++) {
                    mma16816(acc[mt][nt], ahi[mt], bhi[nt]);
                    mma16816(acc[mt][nt], ahi[mt], blo[nt]);
                    mma16816(acc[mt][nt], alo[mt], bhi[nt]);
                }
        }
        __syncthreads();
        if (tid == 0 && kc + 2 < NCH) {
            mbar_expect(mbar + st * 8, STB);
            bulkcp(sbase + st * STB,
                   (const char*)g_Wp + ((size_t)blockIdx.x * NCH + kc + 2) * 32768, 32768,
                   mbar + st * 8);
            bulkcp(sbase + st * STB + 32768, (const char*)g_Bp + (kc + 2) * 8192, 8192, mbar + st * 8);
        }
    }

    // fused epilogue: stats per (row, vtile), no logits store
    float* sOut  = (float*)smem;        // [32][132]
    float* sBias = sOut + 32 * 132;     // [128]
    float* svv   = sBias + 128;         // [128*8]
    int*   sii   = (int*)(svv + 1024);  // [128*8]
    sBias[tid] = b_out[v0 + tid];
#pragma unroll
    for (int mt = 0; mt < 2; mt++)
#pragma unroll
        for (int nt = 0; nt < 4; nt++) {
            int vl = warp * 32 + mt * 16 + (lane >> 2);
            int n0 = nt * 8 + ((lane & 3) << 1);
            sOut[n0 * 132 + vl]           = acc[mt][nt][0];
            sOut[(n0 + 1) * 132 + vl]     = acc[mt][nt][1];
            sOut[n0 * 132 + vl + 8]       = acc[mt][nt][2];
            sOut[(n0 + 1) * 132 + vl + 8] = acc[mt][nt][3];
        }
    __syncthreads();

    int row = tid >> 2, sub = tid & 3, vl0 = sub * 32;
    float m = -FLT_MAX;
#pragma unroll 8
    for (int j = 0; j < 32; j++) m = fmaxf(m, sOut[row * 132 + vl0 + j] + sBias[vl0 + j]);
    m = fmaxf(m, __shfl_xor_sync(0xFFFFFFFFu, m, 1));
    m = fmaxf(m, __shfl_xor_sync(0xFFFFFFFFu, m, 2));
    float ssum = 0.f;
    INS_DECL
#pragma unroll 8
    for (int j = 0; j < 32; j++) {
        float v = sOut[row * 132 + vl0 + j] + sBias[vl0 + j];
        ssum += __expf(v - m);
        INS(v, v0 + vl0 + j);
    }
    ssum += __shfl_xor_sync(0xFFFFFFFFu, ssum, 1);
    ssum += __shfl_xor_sync(0xFFFFFFFFu, ssum, 2);
#pragma unroll
    for (int j = 0; j < 8; j++) { svv[tid * 8 + j] = lv[j]; sii[tid * 8 + j] = li[j]; }
    __syncwarp();
    if (sub < 2) merge_pair(svv, sii, tid * 8, (tid + 2) * 8);
    __syncwarp();
    if (sub < 1) merge_pair(svv, sii, tid * 8, (tid + 1) * 8);
    __syncwarp();
    if (sub == 0) {
        g_pvm[row][blockIdx.x] = m;
        g_pvs[row][blockIdx.x] = ssum;
#pragma unroll
        for (int j = 0; j < 8; j++) {
            g_p8v[row][blockIdx.x][j] = svv[tid * 8 + j];
            g_p8i[row][blockIdx.x][j] = sii[tid * 8 + j];
        }
    }
}

// ---------------- per-step 5: full merge (LSE + top-8 + beam update + history) ----------------
__global__ __launch_bounds__(256) void merge_kernel(int t, const int* __restrict__ eosp) {
    __shared__ float sv[2048]; __shared__ int si[2048];
    __shared__ float s_val[8]; __shared__ int s_tok[8], s_wk[8];
    int b = blockIdx.x, tid = threadIdx.x;
    int s = tid >> 5, lane = tid & 31;
    int eos = eosp[0];

    INS_DECL
    if (t == 0) {
        if (s == 0) {
            int row = b;
            float M = -FLT_MAX;
            for (int vt = lane; vt < NVT; vt += 32) M = fmaxf(M, g_pvm[row][vt]);
#pragma unroll
            for (int o = 16; o >= 1; o >>= 1) M = fmaxf(M, __shfl_xor_sync(0xFFFFFFFFu, M, o));
            float S = 0.f;
            for (int vt = lane; vt < NVT; vt += 32) S += g_pvs[row][vt] * __expf(g_pvm[row][vt] - M);
#pragma unroll
            for (int o = 16; o >= 1; o >>= 1) S += __shfl_xor_sync(0xFFFFFFFFu, S, o);
            float rc = -(M + logf(S));
            for (int vt = lane; vt < NVT; vt += 32)
#pragma unroll
                for (int j = 0; j < 8; j++) INS(g_p8v[row][vt][j] + rc, g_p8i[row][vt][j]);
        }
    } else {
        int row = b * 8 + s;
        float M = -FLT_MAX;
        for (int vt = lane; vt < NVT; vt += 32) M = fmaxf(M, g_pvm[row][vt]);
#pragma unroll
        for (int o = 16; o >= 1; o >>= 1) M = fmaxf(M, __shfl_xor_sync(0xFFFFFFFFu, M, o));
        float S = 0.f;
        for (int vt = lane; vt < NVT; vt += 32) S += g_pvs[row][vt] * __expf(g_pvm[row][vt] - M);
#pragma unroll
        for (int o = 16; o >= 1; o >>= 1) S += __shfl_xor_sync(0xFFFFFFFFu, S, o);
        float rc = g_prevvals[row] - (M + logf(S));
        if (g_prevtok[row] == eos) {
            if (lane == 0) INS(0.0f, s * VV + eos);
        } else {
            for (int vt = lane; vt < NVT; vt += 32)
#pragma unroll
                for (int j = 0; j < 8; j++) INS(g_p8v[row][vt][j] + rc, s * VV + g_p8i[row][vt][j]);
        }
    }
#pragma unroll
    for (int j = 0; j < 8; j++) { sv[tid * 8 + j] = lv[j]; si[tid * 8 + j] = li[j]; }
    __syncthreads();
    merge_lists(sv, si, tid, 128);

    if (tid < 8) {
        float v = sv[tid]; int id = si[tid];
        int tok = (t == 0) ? id : (id % VV);
        int wk  = (t == 0) ? 0  : (id / VV);
        s_val[tid] = v; s_tok[tid] = tok; s_wk[tid] = wk;
        int row = b * 8 + tid;
        g_prevvals[row] = v; g_prevtok[row] = tok; g_last[row] = tok;
        g_which[row] = (t == 0) ? b : (b * 8 + wk);
    }
    __syncthreads();

    if (t == 0) {
        for (int i = tid; i < 8 * TT; i += 256) {
            int k = i >> 6, st = i & 63;
            g_lph[0][(b * 8 + k) * TT + st] = (st == 0) ? s_val[k] : 0.0f;
            g_tkh[0][(b * 8 + k) * TT + st] = (st == 0) ? s_tok[k] : 0;
        }
    } else {
        int nb = t & 1, ob = nb ^ 1;
        for (int i = tid; i < 8 * TT; i += 256) {
            int k = i >> 6, st = i & 63;
            int dst = (b * 8 + k) * TT + st;
            int srcrow = b * 8 + s_wk[k];
            float lp; int tk;
            if (st < t)       { lp = g_lph[ob][srcrow * TT + st]; tk = g_tkh[ob][srcrow * TT + st]; }
            else if (st == t) { lp = s_val[k]; tk = s_tok[k]; }
            else              { lp = 0.0f;     tk = 0; }
            g_lph[nb][dst] = lp; g_tkh[nb][dst] = tk;
        }
    }
}

// ---------------- output ----------------
__global__ void fin_kernel(float* __restrict__ out, int n) {
    int i = blockIdx.x * blockDim.x + threadIdx.x;
    if (i >= n) return;
    if (i < NR * TT)          out[i] = g_lph[1][i];
    else if (i < 2 * NR * TT) out[i] = (float)g_tkh[1][i - NR * TT];
    else                      out[i] = 0.0f;
}

// ---------------- launch ----------------
extern "C" void kernel_launch(void* const* d_in, const int* in_sizes, int n_in,
                              void* d_out, int out_size) {
    const float* encoded   = (const float*)d_in[0];
    const float* embedding = (const float*)d_in[1];
    const float* W_ih      = (const float*)d_in[2];
    const float* W_hh      = (const float*)d_in[3];
    const float* b_ih      = (const float*)d_in[4];
    const float* b_hh      = (const float*)d_in[5];
    const float* W_out     = (const float*)d_in[6];
    const float* b_out     = (const float*)d_in[7];
    const int*   bos       = (const int*)d_in[8];
    const int*   eos       = (const int*)d_in[9];

    cudaFuncSetAttribute(logits_kernel,  cudaFuncAttributeMaxDynamicSharedMemorySize, LG_SMEM);
    cudaFuncSetAttribute(grugemm_kernel, cudaFuncAttributeMaxDynamicSharedMemorySize, GG_SMEM);

    conv_kernel<<<1024, 256>>>(W_out);
    wpack_ih_kernel<<<512, 256>>>(W_ih);
    wpack_hh_kernel<<<1024, 256>>>(W_hh);
    init_kernel<<<1, 32>>>(bos);

    for (int t = 0; t < TT; t++) {
        pack_kernel<<<32, 256>>>(t, encoded, embedding);
        grugemm_kernel<<<144, 128, GG_SMEM>>>();
        gruelem_kernel<<<128, 256>>>(t, encoded, b_ih, b_hh);
        logits_kernel<<<NVT, 128, LG_SMEM>>>(b_out);
        merge_kernel<<<BB, 256>>>(t, eos);
    }
    fin_kernel<<<(out_size + 255) / 256, 256>>>((float*)d_out, out_size);
}